// round 11
// baseline (speedup 1.0000x reference)
#include <cuda_runtime.h>
#include <cuda_bf16.h>
#include <math.h>

// Problem constants
#define BATCH   32
#define C_COMB  448
#define HW_IN   32
#define P_IN    1024
#define HW_FEAT 64
#define N_POS   4096
#define D_PROJ  100
#define OUT_HW  256

// Scratch (device globals; no allocation allowed)
__device__ float g_Wt[C_COMB * D_PROJ];          // [448,100]  W^T
__device__ float g_meanT[N_POS * D_PROJ];        // [4096,100] mean^T
__device__ float g_P[BATCH * P_IN * D_PROJ];     // [32,1024,100]  (p-major, d contiguous)
__device__ float g_dist[BATCH * N_POS];          // [32,4096]

// ---------------------------------------------------------------------------
// Packed fp32x2 helpers (sm_103a FFMA2 — PTX only)
__device__ __forceinline__ void ffma2(unsigned long long& acc,
                                      unsigned long long a, unsigned long long b) {
    asm("fma.rn.f32x2 %0, %1, %2, %0;" : "+l"(acc) : "l"(a), "l"(b));
}
__device__ __forceinline__ unsigned long long pack2(float x, float y) {
    unsigned long long r;
    asm("mov.b64 %0, {%1,%2};" : "=l"(r) : "f"(x), "f"(y));
    return r;
}
__device__ __forceinline__ void unpack2(unsigned long long v, float& lo, float& hi) {
    asm("mov.b64 {%0,%1}, %2;" : "=f"(lo), "=f"(hi) : "l"(v));
}

// ---------------------------------------------------------------------------
__global__ void transpose_w_kernel(const float* __restrict__ proj_w) {
    int i = blockIdx.x * 256 + threadIdx.x;
    if (i < C_COMB * D_PROJ) {
        int c = i / D_PROJ, d = i % D_PROJ;
        g_Wt[i] = proj_w[d * C_COMB + c];
    }
}

__global__ void transpose_mean_kernel(const float* __restrict__ mean) {
    int i = blockIdx.x * 256 + threadIdx.x;
    if (i < N_POS * D_PROJ) {
        int n = i / D_PROJ, d = i % D_PROJ;
        g_meanT[i] = mean[d * N_POS + n];
    }
}

// ---------------------------------------------------------------------------
// Kernel 1: projection GEMM at 32x32 (interp/proj commute).
// P[b,p,d] = sum_c combined[b,c,p] * Wt[c,d] + proj_b[d]
// Warp-broadcast layout: lane = position (32 p per warp-group), each warp owns
// a 28-wide d range; W row values broadcast via LDS.128; FFMA2 accumulators.
// Block = 256 threads: warps 0-3 -> p 0-31 (d ranges 0/28/56/84),
//                      warps 4-7 -> p 32-63.
#define PJ_WPITCH 112

__global__ void __launch_bounds__(256) proj_kernel(
    const float* __restrict__ combined,
    const float* __restrict__ proj_b)
{
    const int b   = blockIdx.y;
    const int p0  = blockIdx.x * 64;
    const int tid = threadIdx.x;
    const int w    = tid >> 5;
    const int lane = tid & 31;
    const int pg   = w >> 2;            // 0/1: which 32-p half
    const int dw   = w & 3;             // d-range index
    const int d0   = dw * 28;

    __shared__ float Xs[32][64];        // [c-chunk][p]
    __shared__ float Ws[32][PJ_WPITCH]; // [c-chunk][d padded]

    // init accumulators with bias (linear: (b + sum) == (sum + b) up to rounding)
    unsigned long long acc[14];
#pragma unroll
    for (int j = 0; j < 14; j++) {
        int d = d0 + 2 * j;
        float lo = (d     < D_PROJ) ? proj_b[d]     : 0.f;
        float hi = (d + 1 < D_PROJ) ? proj_b[d + 1] : 0.f;
        acc[j] = pack2(lo, hi);
    }

    const float* Xg = combined + (size_t)b * C_COMB * P_IN + p0;

    for (int c0 = 0; c0 < C_COMB; c0 += 32) {
        // stage X chunk: 32 c-rows x 64 p (coalesced)
#pragma unroll
        for (int i = tid; i < 32 * 64; i += 256) {
            int kk = i >> 6, pp = i & 63;
            Xs[kk][pp] = Xg[(size_t)(c0 + kk) * P_IN + pp];
        }
        // stage W chunk: 32 c-rows x 112 d (pad zero)
#pragma unroll
        for (int i = tid; i < 32 * PJ_WPITCH; i += 256) {
            int kk = i / PJ_WPITCH, dd = i - kk * PJ_WPITCH;
            Ws[kk][dd] = (dd < D_PROJ) ? g_Wt[(c0 + kk) * D_PROJ + dd] : 0.f;
        }
        __syncthreads();

#pragma unroll 8
        for (int k = 0; k < 32; k++) {
            float a = Xs[k][pg * 32 + lane];              // conflict-free
            unsigned long long ab = pack2(a, a);
            const ulonglong2* Wp = (const ulonglong2*)&Ws[k][d0];  // broadcast
#pragma unroll
            for (int q = 0; q < 7; q++) {
                ulonglong2 Wv = Wp[q];
                ffma2(acc[2 * q],     ab, Wv.x);
                ffma2(acc[2 * q + 1], ab, Wv.y);
            }
        }
        __syncthreads();
    }

    // writeback: lane owns p = p0 + pg*32 + lane, d range [d0, d0+27] (clipped 100)
    {
        int p = p0 + pg * 32 + lane;
        float* O = g_P + (size_t)b * (P_IN * D_PROJ) + (size_t)p * D_PROJ + d0;
        const int nq = (dw == 3) ? 4 : 7;   // d0=84 -> 16 floats covers 84..99
#pragma unroll
        for (int q = 0; q < 7; q++) {
            if (q < nq) {
                float4 v;
                unpack2(acc[2 * q],     v.x, v.y);
                unpack2(acc[2 * q + 1], v.z, v.w);
                *(float4*)(O + 4 * q) = v;
            }
        }
    }
}

// ---------------------------------------------------------------------------
// Kernel 2: per-position Mahalanobis. One block (256 thr) per n.
// lane = batch. Warp w: d-range (w&3)*28, c-range (w>>2)*50 (c-split is linear
// so per-warp partial quadratic sums are exact up to fp reordering).
// smem: Sg[100][112] + dB[32][105] + part[8][32]
#define SG_PITCH 112
#define DB_PITCH 105
#define MAHA_SMEM ((100 * SG_PITCH + BATCH * DB_PITCH + 8 * 32) * 4)

__global__ void __launch_bounds__(256) maha_kernel(
    const float* __restrict__ inv_cov)
{
    extern __shared__ float smem[];
    float* Sg   = smem;                         // [100][112], cols 100..111 zero
    float* dB   = Sg + 100 * SG_PITCH;          // [32][105]  diff[b][d]
    float* part = dB + BATCH * DB_PITCH;        // [8][32]

    const int n    = blockIdx.x;
    const int tid  = threadIdx.x;
    const int w    = tid >> 5;
    const int lane = tid & 31;                  // = batch index
    const int d0   = (w & 3) * 28;
    const int cbeg = (w >> 2) * 50;

    // ---- stage Sigma_n (40KB DRAM), pitch 112, zero-pad ----
    const float* Sgl = inv_cov + (size_t)n * (D_PROJ * D_PROJ);
#pragma unroll 4
    for (int i = tid; i < 100 * SG_PITCH; i += 256) {
        int c = i / SG_PITCH, d = i - c * SG_PITCH;
        Sg[i] = (d < D_PROJ) ? Sgl[c * D_PROJ + d] : 0.f;
    }

    // ---- bilinear corner setup (half-pixel, 32->64) ----
    const int Y = n >> 6, X = n & 63;
    float sy = 0.5f * (float)Y - 0.25f;
    float sx = 0.5f * (float)X - 0.25f;
    float fy = floorf(sy), fx = floorf(sx);
    int y0 = max(0, (int)fy), y1 = min(HW_IN - 1, (int)fy + 1);
    int x0 = max(0, (int)fx), x1 = min(HW_IN - 1, (int)fx + 1);
    float wy1 = sy - fy, wy0 = 1.f - wy1;
    float wx1 = sx - fx, wx0 = 1.f - wx1;
    float w00 = wy0 * wx0, w01 = wy0 * wx1, w10 = wy1 * wx0, w11 = wy1 * wx1;
    int p00 = (y0 * HW_IN + x0) * D_PROJ, p01 = (y0 * HW_IN + x1) * D_PROJ;
    int p10 = (y1 * HW_IN + x0) * D_PROJ, p11 = (y1 * HW_IN + x1) * D_PROJ;

    // ---- diff: gather 4 corners from g_P (L2 resident), coalesced over d ----
    const float* mT = g_meanT + (size_t)n * D_PROJ;
#pragma unroll 2
    for (int i = tid; i < BATCH * D_PROJ; i += 256) {
        int b = i / D_PROJ, d = i - b * D_PROJ;
        const float* Pb = g_P + (size_t)b * (P_IN * D_PROJ) + d;
        float v = w00 * Pb[p00] + w01 * Pb[p01] + w10 * Pb[p10] + w11 * Pb[p11];
        dB[b * DB_PITCH + d] = v - mT[d];      // pitch 105 -> bank 9b+d: distinct
    }
    __syncthreads();

    // ---- GEMM: T[b, d0..d0+27] partial over c in [cbeg, cbeg+50) ----
    unsigned long long acc[14];
#pragma unroll
    for (int j = 0; j < 14; j++) acc[j] = 0ULL;

#pragma unroll 5
    for (int c = cbeg; c < cbeg + 50; c++) {
        float a = dB[lane * DB_PITCH + c];               // conflict-free scalar
        unsigned long long ab = pack2(a, a);
        const ulonglong2* Sp = (const ulonglong2*)&Sg[c * SG_PITCH + d0]; // bcast
#pragma unroll
        for (int q = 0; q < 7; q++) {
            ulonglong2 Sv = Sp[q];
            ffma2(acc[2 * q],     ab, Sv.x);
            ffma2(acc[2 * q + 1], ab, Sv.y);
        }
    }

    // ---- quadratic partial: sum over this warp's d-range ----
    {
        float s = 0.f;
#pragma unroll
        for (int j = 0; j < 14; j++) {
            float lo, hi;
            unpack2(acc[j], lo, hi);
            int d = d0 + 2 * j;
            if (d     < D_PROJ) s += lo * dB[lane * DB_PITCH + d];
            if (d + 1 < D_PROJ) s += hi * dB[lane * DB_PITCH + d + 1];
        }
        part[w * 32 + lane] = s;
    }
    __syncthreads();

    if (tid < BATCH) {
        float s = 0.f;
#pragma unroll
        for (int k = 0; k < 8; k++) s += part[k * 32 + tid];
        g_dist[(size_t)tid * N_POS + n] = s;
    }
}

// ---------------------------------------------------------------------------
// Kernel 3: normalize + bilinear 64->256 upsample (both linear, commute).
__global__ void __launch_bounds__(256) upsample_kernel(
    const float* __restrict__ nmin_p,
    const float* __restrict__ nmax_p,
    float* __restrict__ out)
{
    const int b = blockIdx.y;
    const int i = blockIdx.x * 256 + threadIdx.x;
    const int Y = i >> 8, X = i & 255;

    float sy = 0.25f * (float)Y - 0.375f;
    float sx = 0.25f * (float)X - 0.375f;
    float fy = floorf(sy), fx = floorf(sx);
    int y0 = max(0, (int)fy), y1 = min(HW_FEAT - 1, (int)fy + 1);
    int x0 = max(0, (int)fx), x1 = min(HW_FEAT - 1, (int)fx + 1);
    float wy1 = sy - fy, wy0 = 1.f - wy1;
    float wx1 = sx - fx, wx0 = 1.f - wx1;

    const float* D = g_dist + (size_t)b * N_POS;
    float v = wy0 * (wx0 * D[y0 * HW_FEAT + x0] + wx1 * D[y0 * HW_FEAT + x1])
            + wy1 * (wx0 * D[y1 * HW_FEAT + x0] + wx1 * D[y1 * HW_FEAT + x1]);

    float nmin = *nmin_p, nmax = *nmax_p;
    out[(size_t)b * (OUT_HW * OUT_HW) + i] = (v - nmin) / (nmax - nmin + 1e-8f);
}

// ---------------------------------------------------------------------------
extern "C" void kernel_launch(void* const* d_in, const int* in_sizes, int n_in,
                              void* d_out, int out_size)
{
    const float* combined = (const float*)d_in[0];
    const float* proj_w   = (const float*)d_in[1];
    const float* proj_b   = (const float*)d_in[2];
    const float* mean     = (const float*)d_in[3];
    const float* inv_cov  = (const float*)d_in[4];
    const float* nmin     = (const float*)d_in[5];
    const float* nmax     = (const float*)d_in[6];
    float* out            = (float*)d_out;

    cudaFuncSetAttribute(maha_kernel,
                         cudaFuncAttributeMaxDynamicSharedMemorySize, MAHA_SMEM);

    transpose_w_kernel<<<(C_COMB * D_PROJ + 255) / 256, 256>>>(proj_w);
    transpose_mean_kernel<<<(N_POS * D_PROJ + 255) / 256, 256>>>(mean);
    proj_kernel<<<dim3(P_IN / 64, BATCH), 256>>>(combined, proj_b);
    maha_kernel<<<N_POS, 256, MAHA_SMEM>>>(inv_cov);
    upsample_kernel<<<dim3(OUT_HW * OUT_HW / 256, BATCH), 256>>>(nmin, nmax, out);
}

// round 16
// speedup vs baseline: 1.2585x; 1.2585x over previous
#include <cuda_runtime.h>
#include <math.h>

#define BATCH   32
#define C_COMB  448
#define HW_IN   32
#define P_IN    1024
#define HW_FEAT 64
#define N_POS   4096
#define D_PROJ  100
#define OUT_HW  256

__device__ float g_Wt[C_COMB * D_PROJ];          // [448,100]
__device__ float g_meanT[N_POS * D_PROJ];        // [4096,100]
__device__ float g_P[BATCH * P_IN * D_PROJ];     // [32,1024,100]
__device__ float g_dist[BATCH * N_POS];          // [32,4096]

__device__ __forceinline__ void ffma2(unsigned long long& acc,
                                      unsigned long long a, unsigned long long b) {
    asm("fma.rn.f32x2 %0, %1, %2, %0;" : "+l"(acc) : "l"(a), "l"(b));
}
__device__ __forceinline__ unsigned long long pack2(float x, float y) {
    unsigned long long r;
    asm("mov.b64 %0, {%1,%2};" : "=l"(r) : "f"(x), "f"(y));
    return r;
}
__device__ __forceinline__ void unpack2(unsigned long long v, float& lo, float& hi) {
    asm("mov.b64 {%0,%1}, %2;" : "=f"(lo), "=f"(hi) : "l"(v));
}

// ---------------------------------------------------------------------------
__global__ void transpose_w_kernel(const float* __restrict__ proj_w) {
    int i = blockIdx.x * 256 + threadIdx.x;
    if (i < C_COMB * D_PROJ) {
        int c = i / D_PROJ, d = i % D_PROJ;
        g_Wt[i] = proj_w[d * C_COMB + c];
    }
}

// Tiled transpose: mean [100,4096] -> g_meanT [4096,100]; both sides coalesced.
__global__ void __launch_bounds__(256) transpose_mean_kernel(
    const float* __restrict__ mean)
{
    __shared__ float t[32][33];
    const int nb = blockIdx.x * 32;
    const int db = blockIdx.y * 32;
    const int x  = threadIdx.x & 31;
    const int y0 = threadIdx.x >> 5;
#pragma unroll
    for (int yy = y0; yy < 32; yy += 8) {
        int d = db + yy;
        t[yy][x] = (d < D_PROJ) ? mean[(size_t)d * N_POS + nb + x] : 0.f;
    }
    __syncthreads();
#pragma unroll
    for (int yy = y0; yy < 32; yy += 8) {
        int d = db + x;
        if (d < D_PROJ) g_meanT[(size_t)(nb + yy) * D_PROJ + d] = t[x][yy];
    }
}

// ---------------------------------------------------------------------------
// Kernel 1: projection GEMM at 32x32 (interp/proj commute). Smem/barrier-free.
// Block 256 thr: pgrp = w>>2 (32 p each), dw = w&3. Thread: pq=lane&7 (4 p),
// dq=lane>>3 (8-d sub-range, or c-chunk for tail warp dw==3).
__global__ void __launch_bounds__(256, 3) proj_kernel(
    const float* __restrict__ combined,
    const float* __restrict__ proj_b)
{
    const int b    = blockIdx.y;
    const int tid  = threadIdx.x;
    const int w    = tid >> 5;
    const int lane = tid & 31;
    const int pq   = lane & 7;
    const int dq   = lane >> 3;
    const int pgrp = w >> 2;
    const int dw   = w & 3;
    const int p0   = blockIdx.x * 64 + pgrp * 32 + pq * 4;

    const float* Xb = combined + (size_t)b * (C_COMB * P_IN) + p0;

    if (dw < 3) {
        const int d0 = dw * 32 + dq * 8;            // 0..88
        float4 bA = *(const float4*)(proj_b + d0);
        float4 bB = *(const float4*)(proj_b + d0 + 4);
        unsigned long long binit[4] = {
            pack2(bA.x, bA.y), pack2(bA.z, bA.w),
            pack2(bB.x, bB.y), pack2(bB.z, bB.w) };
        unsigned long long acc[4][4];
#pragma unroll
        for (int j = 0; j < 4; j++)
#pragma unroll
            for (int q = 0; q < 4; q++) acc[j][q] = binit[q];

        const float* Wp = g_Wt + d0;
#pragma unroll 2
        for (int c = 0; c < C_COMB; c++) {
            float4 a = *(const float4*)(Xb + (size_t)c * P_IN);
            const float* wr = Wp + c * D_PROJ;
            ulonglong2 W0 = *(const ulonglong2*)wr;
            ulonglong2 W1 = *(const ulonglong2*)(wr + 4);
            float av[4] = {a.x, a.y, a.z, a.w};
#pragma unroll
            for (int j = 0; j < 4; j++) {
                unsigned long long ab = pack2(av[j], av[j]);
                ffma2(acc[j][0], ab, W0.x);
                ffma2(acc[j][1], ab, W0.y);
                ffma2(acc[j][2], ab, W1.x);
                ffma2(acc[j][3], ab, W1.y);
            }
        }
#pragma unroll
        for (int j = 0; j < 4; j++) {
            float* O = g_P + (size_t)b * (P_IN * D_PROJ)
                           + (size_t)(p0 + j) * D_PROJ + d0;
            float4 o0, o1;
            unpack2(acc[j][0], o0.x, o0.y); unpack2(acc[j][1], o0.z, o0.w);
            unpack2(acc[j][2], o1.x, o1.y); unpack2(acc[j][3], o1.z, o1.w);
            *(float4*)O       = o0;
            *(float4*)(O + 4) = o1;
        }
    } else {
        // tail: d 96..99; c split 4x112 across dq (linear -> exact)
        unsigned long long acc[4][2];
#pragma unroll
        for (int j = 0; j < 4; j++) { acc[j][0] = 0ULL; acc[j][1] = 0ULL; }
        const int cb = dq * 112;
        for (int i = 0; i < 112; i++) {
            int c = cb + i;
            float4 a = *(const float4*)(Xb + (size_t)c * P_IN);
            ulonglong2 W = *(const ulonglong2*)(g_Wt + c * D_PROJ + 96);
            float av[4] = {a.x, a.y, a.z, a.w};
#pragma unroll
            for (int j = 0; j < 4; j++) {
                unsigned long long ab = pack2(av[j], av[j]);
                ffma2(acc[j][0], ab, W.x);
                ffma2(acc[j][1], ab, W.y);
            }
        }
#pragma unroll
        for (int j = 0; j < 4; j++) {
            float f[4];
            unpack2(acc[j][0], f[0], f[1]);
            unpack2(acc[j][1], f[2], f[3]);
#pragma unroll
            for (int k = 0; k < 4; k++) {
                f[k] += __shfl_xor_sync(0xffffffff, f[k], 8);
                f[k] += __shfl_xor_sync(0xffffffff, f[k], 16);
            }
            if (dq == 0) {
                float4 o;
                o.x = f[0] + proj_b[96]; o.y = f[1] + proj_b[97];
                o.z = f[2] + proj_b[98]; o.w = f[3] + proj_b[99];
                float* O = g_P + (size_t)b * (P_IN * D_PROJ)
                               + (size_t)(p0 + j) * D_PROJ + 96;
                *(float4*)O = o;
            }
        }
    }
}

// ---------------------------------------------------------------------------
// Kernel 2: Mahalanobis, one 128-thr block per n. Sigma streamed via LDG.128
// (read-once); only diff in smem (one barrier). Warps 0-2: d = w*32+dq*8 (8 d,
// 4 b per thread); warp 3: d 96..99, c split 4x25 across dq (linear -> exact).
__global__ void __launch_bounds__(128, 6) maha_kernel(
    const float* __restrict__ inv_cov)
{
    __shared__ float dB[BATCH * 105];    // diff[b][d], pitch 105 (bank-clean)
    __shared__ float part[4][32];

    const int n    = blockIdx.x;
    const int tid  = threadIdx.x;
    const int w    = tid >> 5;
    const int lane = tid & 31;
    const int bq   = lane & 7;
    const int dq   = lane >> 3;

    // bilinear corners (half-pixel, 32->64)
    const int Y = n >> 6, X = n & 63;
    float sy = 0.5f * (float)Y - 0.25f;
    float sx = 0.5f * (float)X - 0.25f;
    float fy = floorf(sy), fx = floorf(sx);
    int y0 = max(0, (int)fy), y1 = min(HW_IN - 1, (int)fy + 1);
    int x0 = max(0, (int)fx), x1 = min(HW_IN - 1, (int)fx + 1);
    float wy1 = sy - fy, wy0 = 1.f - wy1;
    float wx1 = sx - fx, wx0 = 1.f - wx1;
    float w00 = wy0 * wx0, w01 = wy0 * wx1, w10 = wy1 * wx0, w11 = wy1 * wx1;
    int p00 = (y0 * HW_IN + x0) * D_PROJ, p01 = (y0 * HW_IN + x1) * D_PROJ;
    int p10 = (y1 * HW_IN + x0) * D_PROJ, p11 = (y1 * HW_IN + x1) * D_PROJ;

    // diff: float4 gathers from g_P (L2-resident), 25 quads x 32 b
    const float* mT = g_meanT + (size_t)n * D_PROJ;
    for (int i = tid; i < BATCH * 25; i += 128) {
        int b = i / 25, q = i - b * 25;
        const float* Pb = g_P + (size_t)b * (P_IN * D_PROJ) + 4 * q;
        float4 v0 = *(const float4*)(Pb + p00);
        float4 v1 = *(const float4*)(Pb + p01);
        float4 v2 = *(const float4*)(Pb + p10);
        float4 v3 = *(const float4*)(Pb + p11);
        float4 m  = *(const float4*)(mT + 4 * q);
        float* dst = dB + b * 105 + 4 * q;
        dst[0] = w00 * v0.x + w01 * v1.x + w10 * v2.x + w11 * v3.x - m.x;
        dst[1] = w00 * v0.y + w01 * v1.y + w10 * v2.y + w11 * v3.y - m.y;
        dst[2] = w00 * v0.z + w01 * v1.z + w10 * v2.z + w11 * v3.z - m.z;
        dst[3] = w00 * v0.w + w01 * v1.w + w10 * v2.w + w11 * v3.w - m.w;
    }
    __syncthreads();

    const float* Sb = inv_cov + (size_t)n * (D_PROJ * D_PROJ);
    float s[4] = {0.f, 0.f, 0.f, 0.f};

    if (w < 3) {
        const int d0 = w * 32 + dq * 8;
        unsigned long long acc[4][4];
#pragma unroll
        for (int j = 0; j < 4; j++)
#pragma unroll
            for (int q = 0; q < 4; q++) acc[j][q] = 0ULL;

#pragma unroll 2
        for (int c = 0; c < D_PROJ; c++) {
            const float* Sr = Sb + c * D_PROJ + d0;
            ulonglong2 S0 = *(const ulonglong2*)Sr;
            ulonglong2 S1 = *(const ulonglong2*)(Sr + 4);
#pragma unroll
            for (int j = 0; j < 4; j++) {
                float a = dB[(bq * 4 + j) * 105 + c];
                unsigned long long ab = pack2(a, a);
                ffma2(acc[j][0], ab, S0.x);
                ffma2(acc[j][1], ab, S0.y);
                ffma2(acc[j][2], ab, S1.x);
                ffma2(acc[j][3], ab, S1.y);
            }
        }
#pragma unroll
        for (int j = 0; j < 4; j++) {
            const float* db = dB + (bq * 4 + j) * 105;
            float t = 0.f;
#pragma unroll
            for (int q = 0; q < 4; q++) {
                float lo, hi;
                unpack2(acc[j][q], lo, hi);
                t += lo * db[d0 + 2 * q] + hi * db[d0 + 2 * q + 1];
            }
            s[j] = t;
        }
    } else {
        unsigned long long acc[4][2];
#pragma unroll
        for (int j = 0; j < 4; j++) { acc[j][0] = 0ULL; acc[j][1] = 0ULL; }
        const int cb = dq * 25;
        for (int i = 0; i < 25; i++) {
            int c = cb + i;
            ulonglong2 S = *(const ulonglong2*)(Sb + c * D_PROJ + 96);
#pragma unroll
            for (int j = 0; j < 4; j++) {
                float a = dB[(bq * 4 + j) * 105 + c];
                unsigned long long ab = pack2(a, a);
                ffma2(acc[j][0], ab, S.x);
                ffma2(acc[j][1], ab, S.y);
            }
        }
#pragma unroll
        for (int j = 0; j < 4; j++) {
            const float* db = dB + (bq * 4 + j) * 105;
            float l0, h0, l1, h1;
            unpack2(acc[j][0], l0, h0);
            unpack2(acc[j][1], l1, h1);
            s[j] = l0 * db[96] + h0 * db[97] + l1 * db[98] + h1 * db[99];
        }
    }

    // reduce over dq (d sub-ranges for w<3, c-chunks for w==3)
#pragma unroll
    for (int j = 0; j < 4; j++) {
        s[j] += __shfl_xor_sync(0xffffffff, s[j], 8);
        s[j] += __shfl_xor_sync(0xffffffff, s[j], 16);
    }
    if (dq == 0) {
#pragma unroll
        for (int j = 0; j < 4; j++) part[w][bq * 4 + j] = s[j];
    }
    __syncthreads();

    if (tid < BATCH) {
        float r = part[0][tid] + part[1][tid] + part[2][tid] + part[3][tid];
        g_dist[(size_t)tid * N_POS + n] = r;
    }
}

// ---------------------------------------------------------------------------
// Kernel 3: normalize + bilinear 64->256 upsample.
__global__ void __launch_bounds__(256) upsample_kernel(
    const float* __restrict__ nmin_p,
    const float* __restrict__ nmax_p,
    float* __restrict__ out)
{
    const int b = blockIdx.y;
    const int i = blockIdx.x * 256 + threadIdx.x;
    const int Y = i >> 8, X = i & 255;

    float sy = 0.25f * (float)Y - 0.375f;
    float sx = 0.25f * (float)X - 0.375f;
    float fy = floorf(sy), fx = floorf(sx);
    int y0 = max(0, (int)fy), y1 = min(HW_FEAT - 1, (int)fy + 1);
    int x0 = max(0, (int)fx), x1 = min(HW_FEAT - 1, (int)fx + 1);
    float wy1 = sy - fy, wy0 = 1.f - wy1;
    float wx1 = sx - fx, wx0 = 1.f - wx1;

    const float* D = g_dist + (size_t)b * N_POS;
    float v = wy0 * (wx0 * D[y0 * HW_FEAT + x0] + wx1 * D[y0 * HW_FEAT + x1])
            + wy1 * (wx0 * D[y1 * HW_FEAT + x0] + wx1 * D[y1 * HW_FEAT + x1]);

    float nmin = *nmin_p, nmax = *nmax_p;
    out[(size_t)b * (OUT_HW * OUT_HW) + i] = (v - nmin) / (nmax - nmin + 1e-8f);
}

// ---------------------------------------------------------------------------
extern "C" void kernel_launch(void* const* d_in, const int* in_sizes, int n_in,
                              void* d_out, int out_size)
{
    const float* combined = (const float*)d_in[0];
    const float* proj_w   = (const float*)d_in[1];
    const float* proj_b   = (const float*)d_in[2];
    const float* mean     = (const float*)d_in[3];
    const float* inv_cov  = (const float*)d_in[4];
    const float* nmin     = (const float*)d_in[5];
    const float* nmax     = (const float*)d_in[6];
    float* out            = (float*)d_out;

    transpose_w_kernel<<<(C_COMB * D_PROJ + 255) / 256, 256>>>(proj_w);
    transpose_mean_kernel<<<dim3(N_POS / 32, 4), 256>>>(mean);
    proj_kernel<<<dim3(P_IN / 64, BATCH), 256>>>(combined, proj_b);
    maha_kernel<<<N_POS, 128>>>(inv_cov);
    upsample_kernel<<<dim3(OUT_HW * OUT_HW / 256, BATCH), 256>>>(nmin, nmax, out);
}

// round 17
// speedup vs baseline: 1.5016x; 1.1932x over previous
#include <cuda_runtime.h>
#include <math.h>

#define BATCH   32
#define C_COMB  448
#define HW_IN   32
#define P_IN    1024
#define HW_FEAT 64
#define N_POS   4096
#define D_PROJ  100
#define OUT_HW  256

#define MAHA_GRID 304          // 2 x 152 SMs (GB300)

__device__ float g_Wt[C_COMB * D_PROJ];          // [448,100]
__device__ float g_meanT[N_POS * D_PROJ];        // [4096,100]
__device__ float g_P[BATCH * P_IN * D_PROJ];     // [32,1024,100]
__device__ float g_dist[BATCH * N_POS];          // [32,4096]

// ---------------------------------------------------------------------------
// fp32x2 packed FMA (PTX-only)
__device__ __forceinline__ void ffma2(unsigned long long& acc,
                                      unsigned long long a, unsigned long long b) {
    asm("fma.rn.f32x2 %0, %1, %2, %0;" : "+l"(acc) : "l"(a), "l"(b));
}
__device__ __forceinline__ unsigned long long pack2(float x, float y) {
    unsigned long long r;
    asm("mov.b64 %0, {%1,%2};" : "=l"(r) : "f"(x), "f"(y));
    return r;
}
__device__ __forceinline__ void unpack2(unsigned long long v, float& lo, float& hi) {
    asm("mov.b64 {%0,%1}, %2;" : "=f"(lo), "=f"(hi) : "l"(v));
}
// cp.async helpers
__device__ __forceinline__ void cp16(void* s, const void* g) {
    unsigned sa = (unsigned)__cvta_generic_to_shared(s);
    asm volatile("cp.async.cg.shared.global [%0], [%1], 16;" :: "r"(sa), "l"(g));
}
__device__ __forceinline__ void cp_commit() {
    asm volatile("cp.async.commit_group;");
}
__device__ __forceinline__ void cp_wait1() {
    asm volatile("cp.async.wait_group 1;");
}

// ---------------------------------------------------------------------------
__global__ void transpose_w_kernel(const float* __restrict__ proj_w) {
    int i = blockIdx.x * 256 + threadIdx.x;
    if (i < C_COMB * D_PROJ) {
        int c = i / D_PROJ, d = i % D_PROJ;
        g_Wt[i] = proj_w[d * C_COMB + c];
    }
}

__global__ void __launch_bounds__(256) transpose_mean_kernel(
    const float* __restrict__ mean)
{
    __shared__ float t[32][33];
    const int nb = blockIdx.x * 32;
    const int db = blockIdx.y * 32;
    const int x  = threadIdx.x & 31;
    const int y0 = threadIdx.x >> 5;
#pragma unroll
    for (int yy = y0; yy < 32; yy += 8) {
        int d = db + yy;
        t[yy][x] = (d < D_PROJ) ? mean[(size_t)d * N_POS + nb + x] : 0.f;
    }
    __syncthreads();
#pragma unroll
    for (int yy = y0; yy < 32; yy += 8) {
        int d = db + x;
        if (d < D_PROJ) g_meanT[(size_t)(nb + yy) * D_PROJ + d] = t[x][yy];
    }
}

// ---------------------------------------------------------------------------
// Kernel 1: projection GEMM (interp/proj commute). cp.async double-buffered
// c-chunks of 16. Block = (b, 64-p tile); warp: pgrp=w>>2 (32 p), dw=w&3
// (d0 = 28*dw, 7 quads; dw==3: 4 quads -> d 84..99). lane = p within group.
__global__ void __launch_bounds__(256, 4) proj_kernel(
    const float* __restrict__ combined,
    const float* __restrict__ proj_b)
{
    __shared__ __align__(16) float Xs[2][16 * 64];    // [c][p]
    __shared__ __align__(16) float Ws[2][16 * 100];   // [c][d]

    const int b    = blockIdx.y;
    const int p0   = blockIdx.x * 64;
    const int tid  = threadIdx.x;
    const int w    = tid >> 5;
    const int lane = tid & 31;
    const int pgrp = w >> 2;
    const int dw   = w & 3;
    const int d0   = dw * 28;
    const int nq   = (dw < 3) ? 7 : 4;

    const float* Xb = combined + (size_t)b * (C_COMB * P_IN) + p0;

    // stage chunk 0
    {
        for (int i = tid; i < 656; i += 256) {
            if (i < 256) {              // X: 16 rows x 16 chunks
                int k = i >> 4, j = i & 15;
                cp16(&Xs[0][k * 64 + j * 4], Xb + (size_t)k * P_IN + j * 4);
            } else {                    // W: 16 rows x 25 chunks
                int r = i - 256, k = r / 25, j = r - k * 25;
                cp16(&Ws[0][k * 100 + j * 4], g_Wt + k * D_PROJ + j * 4);
            }
        }
        cp_commit();
    }

    // acc init with bias
    unsigned long long acc[7];
#pragma unroll
    for (int q = 0; q < 7; q++) {
        if (q < nq) {
            int d = d0 + 4 * q;
            acc[q] = 0ULL;   // placeholder; real init below
        }
    }
    unsigned long long acc2[7];
    {
#pragma unroll
        for (int q = 0; q < 7; q++) {
            if (q < nq) {
                float4 bv = *(const float4*)(proj_b + d0 + 4 * q);
                acc[q]  = pack2(bv.x, bv.y);
                acc2[q] = pack2(bv.z, bv.w);
            } else { acc[q] = 0ULL; acc2[q] = 0ULL; }
        }
    }

    int buf = 0;
    for (int ck = 0; ck < 28; ck++) {
        // prefetch next chunk
        if (ck + 1 < 28) {
            int c0 = (ck + 1) * 16;
            for (int i = tid; i < 656; i += 256) {
                if (i < 256) {
                    int k = i >> 4, j = i & 15;
                    cp16(&Xs[buf ^ 1][k * 64 + j * 4],
                         Xb + (size_t)(c0 + k) * P_IN + j * 4);
                } else {
                    int r = i - 256, k = r / 25, j = r - k * 25;
                    cp16(&Ws[buf ^ 1][k * 100 + j * 4],
                         g_Wt + (c0 + k) * D_PROJ + j * 4);
                }
            }
        }
        cp_commit();
        cp_wait1();
        __syncthreads();

        const float* Xc = Xs[buf];
        const float* Wc = Ws[buf];
#pragma unroll 4
        for (int k = 0; k < 16; k++) {
            float a = Xc[k * 64 + pgrp * 32 + lane];
            unsigned long long ab = pack2(a, a);
            const ulonglong2* Wp = (const ulonglong2*)&Wc[k * 100 + d0];
            if (dw < 3) {
#pragma unroll
                for (int q = 0; q < 7; q++) {
                    ulonglong2 Wv = Wp[q];
                    ffma2(acc[q],  ab, Wv.x);
                    ffma2(acc2[q], ab, Wv.y);
                }
            } else {
#pragma unroll
                for (int q = 0; q < 4; q++) {
                    ulonglong2 Wv = Wp[q];
                    ffma2(acc[q],  ab, Wv.x);
                    ffma2(acc2[q], ab, Wv.y);
                }
            }
        }
        __syncthreads();
        buf ^= 1;
    }

    // writeback
    {
        int p = p0 + pgrp * 32 + lane;
        float* O = g_P + (size_t)b * (P_IN * D_PROJ) + (size_t)p * D_PROJ + d0;
#pragma unroll
        for (int q = 0; q < 7; q++) {
            if (q < nq) {
                float4 o;
                unpack2(acc[q],  o.x, o.y);
                unpack2(acc2[q], o.z, o.w);
                *(float4*)(O + 4 * q) = o;
            }
        }
    }
}

// ---------------------------------------------------------------------------
// Kernel 2: Mahalanobis, persistent blocks, cp.async double-buffered Sigma.
// Block 256 thr handles n = bid, bid+304, ... Warp: ch=w>>2 (50 c),
// dw=w&3 (d0=28*dw; dw==3 -> 4 quads). lane = batch.
// dyn smem: Sg[2][10000] + dB[32*105] + part[8*32] = 94464 B.
#define MAHA_SMEM ((20000 + 32 * 105 + 8 * 32) * 4)

__global__ void __launch_bounds__(256, 2) maha_kernel(
    const float* __restrict__ inv_cov)
{
    extern __shared__ __align__(16) float sm[];
    float* Sg0  = sm;
    float* Sg1  = sm + 10000;
    float* dB   = sm + 20000;            // [32][105]
    float* part = dB + 32 * 105;         // [8][32]

    const int tid  = threadIdx.x;
    const int w    = tid >> 5;
    const int lane = tid & 31;           // batch
    const int ch   = w >> 2;             // c half
    const int dw   = w & 3;
    const int d0   = dw * 28;
    const int nq   = (dw < 3) ? 7 : 4;
    const int cbeg = ch * 50;

    // prefetch first Sigma
    {
        const float* src = inv_cov + (size_t)blockIdx.x * 10000;
        for (int i = tid; i < 2500; i += 256)
            cp16(Sg0 + i * 4, src + i * 4);
        cp_commit();
    }

    int buf = 0;
    for (int n = blockIdx.x; n < N_POS; n += MAHA_GRID) {
        // prefetch next Sigma into other buffer
        int n2 = n + MAHA_GRID;
        if (n2 < N_POS) {
            float* dst = buf ? Sg0 : Sg1;
            const float* src = inv_cov + (size_t)n2 * 10000;
            for (int i = tid; i < 2500; i += 256)
                cp16(dst + i * 4, src + i * 4);
        }
        cp_commit();

        // bilinear corners (half-pixel, 32->64)
        const int Y = n >> 6, X = n & 63;
        float sy = 0.5f * (float)Y - 0.25f;
        float sx = 0.5f * (float)X - 0.25f;
        float fy = floorf(sy), fx = floorf(sx);
        int y0 = max(0, (int)fy), y1 = min(HW_IN - 1, (int)fy + 1);
        int x0 = max(0, (int)fx), x1 = min(HW_IN - 1, (int)fx + 1);
        float wy1 = sy - fy, wy0 = 1.f - wy1;
        float wx1 = sx - fx, wx0 = 1.f - wx1;
        float w00 = wy0 * wx0, w01 = wy0 * wx1, w10 = wy1 * wx0, w11 = wy1 * wx1;
        int p00 = (y0 * HW_IN + x0) * D_PROJ, p01 = (y0 * HW_IN + x1) * D_PROJ;
        int p10 = (y1 * HW_IN + x0) * D_PROJ, p11 = (y1 * HW_IN + x1) * D_PROJ;

        // diff gather (overlaps cp.async DMA)
        const float* mT = g_meanT + (size_t)n * D_PROJ;
        for (int i = tid; i < BATCH * 25; i += 256) {
            int b = i / 25, q = i - b * 25;
            const float* Pb = g_P + (size_t)b * (P_IN * D_PROJ) + 4 * q;
            float4 v0 = *(const float4*)(Pb + p00);
            float4 v1 = *(const float4*)(Pb + p01);
            float4 v2 = *(const float4*)(Pb + p10);
            float4 v3 = *(const float4*)(Pb + p11);
            float4 m  = *(const float4*)(mT + 4 * q);
            float* dst = dB + b * 105 + 4 * q;
            dst[0] = w00 * v0.x + w01 * v1.x + w10 * v2.x + w11 * v3.x - m.x;
            dst[1] = w00 * v0.y + w01 * v1.y + w10 * v2.y + w11 * v3.y - m.y;
            dst[2] = w00 * v0.z + w01 * v1.z + w10 * v2.z + w11 * v3.z - m.z;
            dst[3] = w00 * v0.w + w01 * v1.w + w10 * v2.w + w11 * v3.w - m.w;
        }

        cp_wait1();          // current buffer's Sigma complete (next in flight)
        __syncthreads();

        const float* Sc = buf ? Sg1 : Sg0;
        unsigned long long acc[7], acc2[7];
#pragma unroll
        for (int q = 0; q < 7; q++) { acc[q] = 0ULL; acc2[q] = 0ULL; }

        const float* dRow = dB + 0;      // indexed by lane inside loop
        if (dw < 3) {
#pragma unroll 2
            for (int c = cbeg; c < cbeg + 50; c++) {
                float a = dB[lane * 105 + c];
                unsigned long long ab = pack2(a, a);
                const ulonglong2* Sp = (const ulonglong2*)&Sc[c * D_PROJ + d0];
#pragma unroll
                for (int q = 0; q < 7; q++) {
                    ulonglong2 Sv = Sp[q];
                    ffma2(acc[q],  ab, Sv.x);
                    ffma2(acc2[q], ab, Sv.y);
                }
            }
        } else {
#pragma unroll 2
            for (int c = cbeg; c < cbeg + 50; c++) {
                float a = dB[lane * 105 + c];
                unsigned long long ab = pack2(a, a);
                const ulonglong2* Sp = (const ulonglong2*)&Sc[c * D_PROJ + d0];
#pragma unroll
                for (int q = 0; q < 4; q++) {
                    ulonglong2 Sv = Sp[q];
                    ffma2(acc[q],  ab, Sv.x);
                    ffma2(acc2[q], ab, Sv.y);
                }
            }
        }

        // quadratic partial over this warp's d-range
        {
            const float* db = dB + lane * 105;
            float s = 0.f;
#pragma unroll
            for (int q = 0; q < 7; q++) {
                if (q < nq) {
                    float l0, h0, l1, h1;
                    unpack2(acc[q],  l0, h0);
                    unpack2(acc2[q], l1, h1);
                    int d = d0 + 4 * q;
                    s += l0 * db[d] + h0 * db[d + 1]
                       + l1 * db[d + 2] + h1 * db[d + 3];
                }
            }
            part[w * 32 + lane] = s;
        }
        __syncthreads();

        if (tid < BATCH) {
            float r = 0.f;
#pragma unroll
            for (int k = 0; k < 8; k++) r += part[k * 32 + tid];
            g_dist[(size_t)tid * N_POS + n] = r;
        }
        __syncthreads();     // protect dB/part/Sg reuse next iteration
        buf ^= 1;
    }
}

// ---------------------------------------------------------------------------
// Kernel 3: normalize + bilinear 64->256 upsample.
__global__ void __launch_bounds__(256) upsample_kernel(
    const float* __restrict__ nmin_p,
    const float* __restrict__ nmax_p,
    float* __restrict__ out)
{
    const int b = blockIdx.y;
    const int i = blockIdx.x * 256 + threadIdx.x;
    const int Y = i >> 8, X = i & 255;

    float sy = 0.25f * (float)Y - 0.375f;
    float sx = 0.25f * (float)X - 0.375f;
    float fy = floorf(sy), fx = floorf(sx);
    int y0 = max(0, (int)fy), y1 = min(HW_FEAT - 1, (int)fy + 1);
    int x0 = max(0, (int)fx), x1 = min(HW_FEAT - 1, (int)fx + 1);
    float wy1 = sy - fy, wy0 = 1.f - wy1;
    float wx1 = sx - fx, wx0 = 1.f - wx1;

    const float* D = g_dist + (size_t)b * N_POS;
    float v = wy0 * (wx0 * D[y0 * HW_FEAT + x0] + wx1 * D[y0 * HW_FEAT + x1])
            + wy1 * (wx0 * D[y1 * HW_FEAT + x0] + wx1 * D[y1 * HW_FEAT + x1]);

    float nmin = *nmin_p, nmax = *nmax_p;
    out[(size_t)b * (OUT_HW * OUT_HW) + i] = (v - nmin) / (nmax - nmin + 1e-8f);
}

// ---------------------------------------------------------------------------
extern "C" void kernel_launch(void* const* d_in, const int* in_sizes, int n_in,
                              void* d_out, int out_size)
{
    const float* combined = (const float*)d_in[0];
    const float* proj_w   = (const float*)d_in[1];
    const float* proj_b   = (const float*)d_in[2];
    const float* mean     = (const float*)d_in[3];
    const float* inv_cov  = (const float*)d_in[4];
    const float* nmin     = (const float*)d_in[5];
    const float* nmax     = (const float*)d_in[6];
    float* out            = (float*)d_out;

    cudaFuncSetAttribute(maha_kernel,
                         cudaFuncAttributeMaxDynamicSharedMemorySize, MAHA_SMEM);

    transpose_w_kernel<<<(C_COMB * D_PROJ + 255) / 256, 256>>>(proj_w);
    transpose_mean_kernel<<<dim3(N_POS / 32, 4), 256>>>(mean);
    proj_kernel<<<dim3(P_IN / 64, BATCH), 256>>>(combined, proj_b);
    maha_kernel<<<MAHA_GRID, 256, MAHA_SMEM>>>(inv_cov);
    upsample_kernel<<<dim3(OUT_HW * OUT_HW / 256, BATCH), 256>>>(nmin, nmax, out);
}